// round 2
// baseline (speedup 1.0000x reference)
#include <cuda_runtime.h>

// Problem shape (fixed by the dataset reference)
#define BB      16
#define TT      256
#define NPTS    2048
#define TCHUNK  64
#define NCHUNKS (TT / TCHUNK)          // 4
#define BC      (BB * NCHUNKS)         // 64 partial groups
#define THREADS 256

// Partial per-point stats: g_part[bc][stat][n], stat:
//  0..2 : sum m*pred_c     3..5 : sum m*pred_c^2
//  6..8 : sum m*gt_c       9..11: sum m*gt_c^2
//  12   : count
__device__ float g_part[BC * 13 * NPTS];        // 6.8 MB, fully overwritten each replay
__device__ float g_stats2[13 * NPTS];           // reduced stats
__device__ float g_pscal[(BB * NCHUNKS * NPTS / THREADS) * 4];  // per-CTA: nv, recon, vels, velc

__global__ __launch_bounds__(THREADS) void main_k(
    const float* __restrict__ pred,
    const float* __restrict__ gt,
    const float* __restrict__ vis)
{
    const int tid   = blockIdx.x * THREADS + threadIdx.x;
    const int n     = tid & (NPTS - 1);
    const int lane  = n & 31;
    const int n0    = n & ~31;             // warp's point block base
    const int bc    = tid >> 11;
    const int chunk = bc & (NCHUNKS - 1);
    const int b     = bc >> 2;             // NCHUNKS = 4
    const int t0    = chunk * TCHUNK;

    // --- shuffle-transpose constants (loop invariant) ---
    // target j: receive flat 3*lane+j from src lane (3*lane+j)&31, reg (3*lane+j)>>5
    // provider: this lane presents reg pq_j for shuffle j, where
    //   l' = (11*(lane-j)) & 31  (11 = 3^-1 mod 32),  pq_j = (3*l'+j) >> 5
    int src0 = (3 * lane + 0) & 31, src1 = (3 * lane + 1) & 31, src2 = (3 * lane + 2) & 31;
    int pq0 = (3 * ((11 * (lane - 0)) & 31) + 0) >> 5;
    int pq1 = (3 * ((11 * (lane - 1)) & 31) + 1) >> 5;
    int pq2 = (3 * ((11 * (lane - 2)) & 31) + 2) >> 5;

    float sxp0=0.f,sxp1=0.f,sxp2=0.f, ssp0=0.f,ssp1=0.f,ssp2=0.f;
    float sxg0=0.f,sxg1=0.f,sxg2=0.f, ssg0=0.f,ssg1=0.f,ssg2=0.f;
    float cnt=0.f, recon=0.f, vels=0.f, velc=0.f;

    // previous-frame diff state (d = pred - gt), register carried
    float pdx=0.f, pdy=0.f, pdz=0.f, pm=0.f;
    if (t0 > 0) {
        int vi = (b * TT + (t0 - 1)) * NPTS + n;
        int pi = vi * 3;
        pm  = (vis[vi] > 0.5f) ? 1.f : 0.f;
        pdx = pred[pi]     - gt[pi];
        pdy = pred[pi + 1] - gt[pi + 1];
        pdz = pred[pi + 2] - gt[pi + 2];
    }

    const unsigned fmask = 0xffffffffu;

#pragma unroll 4
    for (int t = t0; t < t0 + TCHUNK; ++t) {
        const int vbase = (b * TT + t) * NPTS + n0;
        const int pbase = vbase * 3;

        float m = (vis[vbase + lane] > 0.5f) ? 1.f : 0.f;

        // dense warp loads: 3 consecutive 128B segments per array
        float a0 = pred[pbase + lane];
        float a1 = pred[pbase + 32 + lane];
        float a2 = pred[pbase + 64 + lane];
        float c0 = gt[pbase + lane];
        float c1 = gt[pbase + 32 + lane];
        float c2 = gt[pbase + 64 + lane];

        // transpose: each lane gathers its point's x,y,z
        float pv0 = (pq0 == 0) ? a0 : ((pq0 == 1) ? a1 : a2);
        float pv1 = (pq1 == 0) ? a0 : ((pq1 == 1) ? a1 : a2);
        float pv2 = (pq2 == 0) ? a0 : ((pq2 == 1) ? a1 : a2);
        float px = __shfl_sync(fmask, pv0, src0);
        float py = __shfl_sync(fmask, pv1, src1);
        float pz = __shfl_sync(fmask, pv2, src2);

        float gv0 = (pq0 == 0) ? c0 : ((pq0 == 1) ? c1 : c2);
        float gv1 = (pq1 == 0) ? c0 : ((pq1 == 1) ? c1 : c2);
        float gv2 = (pq2 == 0) ? c0 : ((pq2 == 1) ? c1 : c2);
        float gx = __shfl_sync(fmask, gv0, src0);
        float gy = __shfl_sync(fmask, gv1, src1);
        float gz = __shfl_sync(fmask, gv2, src2);

        // reconstruction (z weighted 2x)
        float dx = px - gx, dy = py - gy, dz = pz - gz;
        recon += m * (dx * dx + dy * dy + 2.f * dz * dz);
        cnt   += m;

        // identity stats
        float mpx = m * px, mpy = m * py, mpz = m * pz;
        float mgx = m * gx, mgy = m * gy, mgz = m * gz;
        sxp0 += mpx; ssp0 += mpx * px;
        sxp1 += mpy; ssp1 += mpy * py;
        sxp2 += mpz; ssp2 += mpz * pz;
        sxg0 += mgx; ssg0 += mgx * gx;
        sxg1 += mgy; ssg1 += mgy * gy;
        sxg2 += mgz; ssg2 += mgz * gz;

        // temporal: (p_t - p_{t-1}) - (g_t - g_{t-1}) = d_t - d_{t-1}
        float vm = m * pm;
        float tx = dx - pdx, ty = dy - pdy, tz = dz - pdz;
        vels += vm * (tx * tx + ty * ty + tz * tz);
        velc += vm;

        pdx = dx; pdy = dy; pdz = dz; pm = m;
    }

    // per-point stats -> partial buffer (plain coalesced stores, no atomics)
    float* gp = &g_part[bc * 13 * NPTS + n];
    gp[ 0 * NPTS] = sxp0;  gp[ 1 * NPTS] = sxp1;  gp[ 2 * NPTS] = sxp2;
    gp[ 3 * NPTS] = ssp0;  gp[ 4 * NPTS] = ssp1;  gp[ 5 * NPTS] = ssp2;
    gp[ 6 * NPTS] = sxg0;  gp[ 7 * NPTS] = sxg1;  gp[ 8 * NPTS] = sxg2;
    gp[ 9 * NPTS] = ssg0;  gp[10 * NPTS] = ssg1;  gp[11 * NPTS] = ssg2;
    gp[12 * NPTS] = cnt;

    // scalar partials: warp reduce -> smem -> one store per CTA
    __shared__ float swarp[8][4];
#pragma unroll
    for (int o = 16; o > 0; o >>= 1) {
        cnt   += __shfl_down_sync(fmask, cnt,   o);
        recon += __shfl_down_sync(fmask, recon, o);
        vels  += __shfl_down_sync(fmask, vels,  o);
        velc  += __shfl_down_sync(fmask, velc,  o);
    }
    int w = threadIdx.x >> 5;
    if ((threadIdx.x & 31) == 0) {
        swarp[w][0] = cnt; swarp[w][1] = recon; swarp[w][2] = vels; swarp[w][3] = velc;
    }
    __syncthreads();
    if (threadIdx.x == 0) {
        float s0 = 0.f, s1 = 0.f, s2 = 0.f, s3 = 0.f;
#pragma unroll
        for (int i = 0; i < 8; ++i) {
            s0 += swarp[i][0]; s1 += swarp[i][1]; s2 += swarp[i][2]; s3 += swarp[i][3];
        }
        float* ps = &g_pscal[blockIdx.x * 4];
        ps[0] = s0; ps[1] = s1; ps[2] = s2; ps[3] = s3;
    }
}

// Reduce partials over bc: thread per (stat, n)
__global__ __launch_bounds__(THREADS) void reduce_k() {
    int idx = blockIdx.x * THREADS + threadIdx.x;   // 13*2048 threads
    if (idx >= 13 * NPTS) return;
    float s = 0.f;
#pragma unroll 8
    for (int bc = 0; bc < BC; ++bc)
        s += g_part[bc * 13 * NPTS + idx];
    g_stats2[idx] = s;
}

__global__ __launch_bounds__(1024) void final_k(float* __restrict__ out) {
    __shared__ float red[1024];
    __shared__ float reds[4][1024];
    const int tid = threadIdx.x;
    const int NCTA = BB * NCHUNKS * NPTS / THREADS;  // 512

    // identity per-point contributions
    float local = 0.f;
#pragma unroll
    for (int n = tid; n < NPTS; n += 1024) {
        float c = g_stats2[12 * NPTS + n];
        if (c > 1.f) {
            float inv_n  = 1.f / c;
            float inv_n1 = 1.f / (c - 1.f);
            float adsum = 0.f, vgsum = 0.f;
#pragma unroll
            for (int k = 0; k < 3; ++k) {
                float sp  = g_stats2[(0 + k) * NPTS + n];
                float ssp = g_stats2[(3 + k) * NPTS + n];
                float sg  = g_stats2[(6 + k) * NPTS + n];
                float ssg = g_stats2[(9 + k) * NPTS + n];
                float vp = (ssp - sp * sp * inv_n) * inv_n1;
                float vg = (ssg - sg * sg * inv_n) * inv_n1;
                adsum += fabsf(vp - vg);
                vgsum += vg;
            }
            local += adsum / (vgsum + 1e-6f);
        }
    }

    // scalar partial sums
    float s0 = 0.f, s1 = 0.f, s2 = 0.f, s3 = 0.f;
    if (tid < NCTA) {
        const float* ps = &g_pscal[tid * 4];
        s0 = ps[0]; s1 = ps[1]; s2 = ps[2]; s3 = ps[3];
    }

    red[tid] = local;
    reds[0][tid] = s0; reds[1][tid] = s1; reds[2][tid] = s2; reds[3][tid] = s3;
    __syncthreads();
#pragma unroll
    for (int s = 512; s > 0; s >>= 1) {
        if (tid < s) {
            red[tid]     += red[tid + s];
            reds[0][tid] += reds[0][tid + s];
            reds[1][tid] += reds[1][tid + s];
            reds[2][tid] += reds[2][tid + s];
            reds[3][tid] += reds[3][tid + s];
        }
        __syncthreads();
    }

    if (tid == 0) {
        float identity = red[0] / (float)NPTS;
        float nv = reds[0][0], rs = reds[1][0], vs = reds[2][0], vc = reds[3][0];
        float recon    = (nv > 0.f) ? rs / fmaxf(nv, 1.f) : 0.f;
        float temporal = (vc > 0.f) ? vs / fmaxf(vc, 1.f) : 0.f;

        // adaptive re-weighting (faithful to reference)
        float rl = recon, tl = temporal, il = identity;
        bool  all_pos = (rl > 0.f) && (tl > 0.f) && (il > 0.f);
        float maxc    = fmaxf(rl, fmaxf(tl, il));
        float target  = maxc / 3.f;
        float thresh  = 10.f * target;
        float rw = (all_pos && rl > thresh) ? 1.0f * target / fmaxf(rl, 1e-30f) : 1.0f;
        float tw = (all_pos && tl > thresh) ? 0.5f * target / fmaxf(tl, 1e-30f) : 0.5f;
        float iw = (all_pos && il > thresh) ? 0.1f * target / fmaxf(il, 1e-30f) : 0.1f;

        out[0] = rw * recon + tw * temporal + iw * identity;
        out[1] = recon;
        out[2] = temporal;
        out[3] = identity;
    }
}

extern "C" void kernel_launch(void* const* d_in, const int* in_sizes, int n_in,
                              void* d_out, int out_size)
{
    const float* pred = (const float*)d_in[0];
    const float* gt   = (const float*)d_in[1];
    const float* vis  = (const float*)d_in[2];
    float* out = (float*)d_out;
    (void)in_sizes; (void)n_in; (void)out_size;

    int mgrid = (BB * NCHUNKS * NPTS) / THREADS;   // 512 blocks
    main_k<<<mgrid, THREADS>>>(pred, gt, vis);

    int rgrid = (13 * NPTS + THREADS - 1) / THREADS;  // 104 blocks
    reduce_k<<<rgrid, THREADS>>>();

    final_k<<<1, 1024>>>(out);
}

// round 3
// speedup vs baseline: 1.4343x; 1.4343x over previous
#include <cuda_runtime.h>

// Problem shape (fixed by the dataset reference)
#define BB      16
#define TT      256
#define NPTS    2048
#define NF      (NPTS * 3)             // 6144 flat (point,coord) indices
#define TCHUNK  32
#define NCHUNKS (TT / TCHUNK)          // 8
#define BC      (BB * NCHUNKS)         // 128 partial groups
#define THREADS 256
#define CPB     (NF / THREADS)         // 24 CTAs per bc group
#define NCTA    (BC * CPB)             // 3072 main CTAs

// Partial per-(n,c) stats: g_part[bc][stat][flat], stat: 0 sxp, 1 ssp, 2 sxg, 3 ssg, 4 cnt
__device__ float g_part[BC * 5 * NF];          // 15.7 MB, fully overwritten each replay
__device__ float g_stats2[5 * NF];             // reduced stats
__device__ float g_pscal[NCTA * 4];            // per-CTA: cnt3x, recon, vels, velc3x

__global__ __launch_bounds__(THREADS) void main_k(
    const float* __restrict__ pred,
    const float* __restrict__ gt,
    const float* __restrict__ vis)
{
    const int bc    = blockIdx.x / CPB;
    const int flat  = (blockIdx.x % CPB) * THREADS + threadIdx.x;
    const int chunk = bc & (NCHUNKS - 1);
    const int b     = bc >> 3;                 // NCHUNKS = 8
    const int t0    = chunk * TCHUNK;

    const int   n = flat / 3;                  // point index (const-div)
    const int   c = flat - 3 * n;              // coord
    const float w = (c == 2) ? 2.f : 1.f;      // z weighted 2x (recon only)

    const int row0 = b * TT + t0;
    const float* pp = pred + (long)row0 * NF + flat;
    const float* gp = gt   + (long)row0 * NF + flat;
    const float* vp = vis  + (long)row0 * NPTS + n;

    float sxp = 0.f, ssp = 0.f, sxg = 0.f, ssg = 0.f, cnt = 0.f;
    float recon = 0.f, vels = 0.f, velc = 0.f;

    // previous-frame diff state (d = pred - gt) for temporal term
    float pd = 0.f, pm = 0.f;
    if (t0 > 0) {
        pm = (vp[-NPTS] > 0.5f) ? 1.f : 0.f;
        pd = pp[-NF] - gp[-NF];
    }

#pragma unroll 4
    for (int t = 0; t < TCHUNK; ++t) {
        float m = (vp[0] > 0.5f) ? 1.f : 0.f;
        float p = pp[0];
        float g = gp[0];
        pp += NF; gp += NF; vp += NPTS;

        float d = p - g;
        recon += w * (m * d) * d;
        cnt   += m;

        float mp = m * p, mg = m * g;
        sxp += mp;  ssp += mp * p;
        sxg += mg;  ssg += mg * g;

        float vm = m * pm;
        float tv = d - pd;
        vels += (vm * tv) * tv;
        velc += vm;

        pd = d; pm = m;
    }

    // per-(n,c) stats -> partial buffer (plain coalesced stores, no atomics)
    float* out = &g_part[bc * 5 * NF + flat];
    out[0 * NF] = sxp;
    out[1 * NF] = ssp;
    out[2 * NF] = sxg;
    out[3 * NF] = ssg;
    out[4 * NF] = cnt;

    // scalar partials: warp reduce -> smem -> one store per CTA
    const unsigned fmask = 0xffffffffu;
    __shared__ float swarp[8][4];
#pragma unroll
    for (int o = 16; o > 0; o >>= 1) {
        cnt   += __shfl_down_sync(fmask, cnt,   o);
        recon += __shfl_down_sync(fmask, recon, o);
        vels  += __shfl_down_sync(fmask, vels,  o);
        velc  += __shfl_down_sync(fmask, velc,  o);
    }
    int wd = threadIdx.x >> 5;
    if ((threadIdx.x & 31) == 0) {
        swarp[wd][0] = cnt; swarp[wd][1] = recon; swarp[wd][2] = vels; swarp[wd][3] = velc;
    }
    __syncthreads();
    if (threadIdx.x == 0) {
        float s0 = 0.f, s1 = 0.f, s2 = 0.f, s3 = 0.f;
#pragma unroll
        for (int i = 0; i < 8; ++i) {
            s0 += swarp[i][0]; s1 += swarp[i][1]; s2 += swarp[i][2]; s3 += swarp[i][3];
        }
        float* ps = &g_pscal[blockIdx.x * 4];
        ps[0] = s0; ps[1] = s1; ps[2] = s2; ps[3] = s3;
    }
}

// Reduce partials over bc groups: one thread per (stat, flat)
__global__ __launch_bounds__(THREADS) void reduce_k() {
    int idx = blockIdx.x * THREADS + threadIdx.x;   // 5*6144 = 30720 threads
    if (idx >= 5 * NF) return;
    float s = 0.f;
#pragma unroll 8
    for (int bc = 0; bc < BC; ++bc)
        s += g_part[bc * 5 * NF + idx];
    g_stats2[idx] = s;
}

__global__ __launch_bounds__(1024) void final_k(float* __restrict__ out) {
    __shared__ float red[1024];
    __shared__ float reds[4][1024];
    const int tid = threadIdx.x;

    // identity per-point contributions
    float local = 0.f;
#pragma unroll
    for (int n = tid; n < NPTS; n += 1024) {
        float cn = g_stats2[4 * NF + 3 * n];    // count (same for all 3 coords)
        if (cn > 1.f) {
            float inv_n  = 1.f / cn;
            float inv_n1 = 1.f / (cn - 1.f);
            float adsum = 0.f, vgsum = 0.f;
#pragma unroll
            for (int k = 0; k < 3; ++k) {
                float sp  = g_stats2[0 * NF + 3 * n + k];
                float ssp = g_stats2[1 * NF + 3 * n + k];
                float sg  = g_stats2[2 * NF + 3 * n + k];
                float ssg = g_stats2[3 * NF + 3 * n + k];
                float vp = (ssp - sp * sp * inv_n) * inv_n1;
                float vg = (ssg - sg * sg * inv_n) * inv_n1;
                adsum += fabsf(vp - vg);
                vgsum += vg;
            }
            local += adsum / (vgsum + 1e-6f);
        }
    }

    // scalar partial sums over NCTA = 3072 entries (3 per thread)
    float s0 = 0.f, s1 = 0.f, s2 = 0.f, s3 = 0.f;
#pragma unroll
    for (int i = tid; i < NCTA; i += 1024) {
        const float* ps = &g_pscal[i * 4];
        s0 += ps[0]; s1 += ps[1]; s2 += ps[2]; s3 += ps[3];
    }

    red[tid] = local;
    reds[0][tid] = s0; reds[1][tid] = s1; reds[2][tid] = s2; reds[3][tid] = s3;
    __syncthreads();
#pragma unroll
    for (int s = 512; s > 0; s >>= 1) {
        if (tid < s) {
            red[tid]     += red[tid + s];
            reds[0][tid] += reds[0][tid + s];
            reds[1][tid] += reds[1][tid + s];
            reds[2][tid] += reds[2][tid + s];
            reds[3][tid] += reds[3][tid + s];
        }
        __syncthreads();
    }

    if (tid == 0) {
        float identity = red[0] / (float)NPTS;
        // counts were accumulated 3x (once per coord) -> exact /3
        float nv = reds[0][0] / 3.0f;
        float rs = reds[1][0];
        float vs = reds[2][0];
        float vc = reds[3][0] / 3.0f;
        float recon    = (nv > 0.f) ? rs / fmaxf(nv, 1.f) : 0.f;
        float temporal = (vc > 0.f) ? vs / fmaxf(vc, 1.f) : 0.f;

        // adaptive re-weighting (faithful to reference)
        float rl = recon, tl = temporal, il = identity;
        bool  all_pos = (rl > 0.f) && (tl > 0.f) && (il > 0.f);
        float maxc    = fmaxf(rl, fmaxf(tl, il));
        float target  = maxc / 3.f;
        float thresh  = 10.f * target;
        float rw = (all_pos && rl > thresh) ? 1.0f * target / fmaxf(rl, 1e-30f) : 1.0f;
        float tw = (all_pos && tl > thresh) ? 0.5f * target / fmaxf(tl, 1e-30f) : 0.5f;
        float iw = (all_pos && il > thresh) ? 0.1f * target / fmaxf(il, 1e-30f) : 0.1f;

        out[0] = rw * recon + tw * temporal + iw * identity;
        out[1] = recon;
        out[2] = temporal;
        out[3] = identity;
    }
}

extern "C" void kernel_launch(void* const* d_in, const int* in_sizes, int n_in,
                              void* d_out, int out_size)
{
    const float* pred = (const float*)d_in[0];
    const float* gt   = (const float*)d_in[1];
    const float* vis  = (const float*)d_in[2];
    float* out = (float*)d_out;
    (void)in_sizes; (void)n_in; (void)out_size;

    main_k<<<NCTA, THREADS>>>(pred, gt, vis);               // 3072 blocks

    int rgrid = (5 * NF + THREADS - 1) / THREADS;           // 120 blocks
    reduce_k<<<rgrid, THREADS>>>();

    final_k<<<1, 1024>>>(out);
}